// round 10
// baseline (speedup 1.0000x reference)
#include <cuda_runtime.h>
#include <cuda_bf16.h>
#include <math.h>
#include <stdint.h>

#define BB   8
#define NN   2048
#define DIMM 1024
#define HH   16
#define MM   (BB*NN)   /* 16384 rows */
#define CH   16        /* scan time-chunk */

// ---------------- scratch (static device globals; no allocation) ----------------
__device__ float g_pq[(size_t)MM*DIMM];
__device__ float g_pk[(size_t)MM*DIMM];
__device__ float g_pv[(size_t)MM*DIMM];
__device__ float g_q [(size_t)MM*DIMM];
__device__ float g_k [(size_t)MM*DIMM];
__device__ float g_v [(size_t)MM*DIMM];
__device__ float g_o [(size_t)MM*DIMM];
__device__ float g_a [(size_t)MM*HH];
__device__ float g_b [(size_t)MM*HH];
__device__ __align__(256) __nv_bfloat16 g_xhi[(size_t)MM*DIMM];
__device__ __align__(256) __nv_bfloat16 g_xlo[(size_t)MM*DIMM];
__device__ __align__(256) __nv_bfloat16 g_ohi[(size_t)MM*DIMM];
__device__ __align__(256) __nv_bfloat16 g_olo[(size_t)MM*DIMM];
__device__ __align__(256) __nv_bfloat16 g_w3hi[(size_t)3*DIMM*DIMM];
__device__ __align__(256) __nv_bfloat16 g_w3lo[(size_t)3*DIMM*DIMM];
__device__ __align__(256) __nv_bfloat16 g_wohi[(size_t)DIMM*DIMM];
__device__ __align__(256) __nv_bfloat16 g_wolo[(size_t)DIMM*DIMM];

// ---------------- helpers ----------------
__device__ __forceinline__ float siluf(float x){ return x / (1.f + __expf(-x)); }
__device__ __forceinline__ float sigmf(float x){ return 1.f / (1.f + __expf(-x)); }

__device__ __forceinline__ uint32_t smem_u32(const void* p){
  uint32_t a;
  asm("{ .reg .u64 t; cvta.to.shared.u64 t, %1; cvt.u32.u64 %0, t; }" : "=r"(a) : "l"(p));
  return a;
}
__device__ __forceinline__ void ldsm4(uint32_t* d, uint32_t addr){
  asm volatile("ldmatrix.sync.aligned.m8n8.x4.shared.b16 {%0,%1,%2,%3}, [%4];"
    : "=r"(d[0]),"=r"(d[1]),"=r"(d[2]),"=r"(d[3]) : "r"(addr));
}
__device__ __forceinline__ void mma16816(float* d, const uint32_t* a, const uint32_t* b){
  asm volatile("mma.sync.aligned.m16n8k16.row.col.f32.bf16.bf16.f32 "
    "{%0,%1,%2,%3}, {%4,%5,%6,%7}, {%8,%9}, {%0,%1,%2,%3};"
    : "+f"(d[0]),"+f"(d[1]),"+f"(d[2]),"+f"(d[3])
    : "r"(a[0]),"r"(a[1]),"r"(a[2]),"r"(a[3]), "r"(b[0]),"r"(b[1]));
}

// ---------------- bf16 hi/lo split ----------------
__global__ __launch_bounds__(256) void split_kernel(
    const float* __restrict__ X, __nv_bfloat16* __restrict__ Hp, __nv_bfloat16* __restrict__ Lp, int n4)
{
  int i = blockIdx.x * 256 + threadIdx.x;
  if (i >= n4) return;
  float4 v = ((const float4*)X)[i];
  __nv_bfloat16 h0 = __float2bfloat16(v.x), h1 = __float2bfloat16(v.y);
  __nv_bfloat16 h2 = __float2bfloat16(v.z), h3 = __float2bfloat16(v.w);
  __nv_bfloat16 l0 = __float2bfloat16(v.x - __bfloat162float(h0));
  __nv_bfloat16 l1 = __float2bfloat16(v.y - __bfloat162float(h1));
  __nv_bfloat16 l2 = __float2bfloat16(v.z - __bfloat162float(h2));
  __nv_bfloat16 l3 = __float2bfloat16(v.w - __bfloat162float(h3));
  __nv_bfloat162* Hq = (__nv_bfloat162*)Hp;
  __nv_bfloat162* Lq = (__nv_bfloat162*)Lp;
  Hq[2*i]   = __nv_bfloat162(h0, h1);
  Hq[2*i+1] = __nv_bfloat162(h2, h3);
  Lq[2*i]   = __nv_bfloat162(l0, l1);
  Lq[2*i+1] = __nv_bfloat162(l2, l3);
}

// ---------------- HMMA bf16-split GEMM body (shared by gemm_qkv / gemm_mma) --
#define KC 32
#define ASTR 40          /* bf16 row stride (80 B, 16B-mult, conflict-free) */

__device__ __forceinline__ void gemm_body(
    const __nv_bfloat16* __restrict__ Ahi, const __nv_bfloat16* __restrict__ Alo,
    const __nv_bfloat16* __restrict__ Whi, const __nv_bfloat16* __restrict__ Wlo,
    const float* __restrict__ bias, float* __restrict__ C, int doSilu,
    int m0, int n0)
{
  __shared__ __nv_bfloat16 sAh[128*ASTR], sAl[128*ASTR], sWh[128*ASTR], sWl[128*ASTR];

  const int tid  = threadIdx.x;
  const int w    = tid >> 5;
  const int lane = tid & 31;
  const int warp_m = w >> 2;        // 0..1
  const int warp_n = w & 3;         // 0..3

  const int r    = tid >> 1;
  const int gcol = (tid & 1) << 4;  // 0 or 16
  const __nv_bfloat16* pAh = Ahi + (size_t)(m0 + r) * DIMM + gcol;
  const __nv_bfloat16* pAl = Alo + (size_t)(m0 + r) * DIMM + gcol;
  const __nv_bfloat16* pWh = Whi + (size_t)(n0 + r) * DIMM + gcol;
  const __nv_bfloat16* pWl = Wlo + (size_t)(n0 + r) * DIMM + gcol;
  const int soff = r * ASTR + gcol;

  const int mmat = lane >> 3, rr = lane & 7;
  const int arowb = warp_m * 64 + ((mmat & 1) << 3) + rr;
  const int acols = (mmat >> 1) << 3;
  const int browb = warp_n * 32 + ((mmat >> 1) << 3) + rr;
  const int bcols = (mmat & 1) << 3;
  const uint32_t sAhB = smem_u32(sAh), sAlB = smem_u32(sAl);
  const uint32_t sWhB = smem_u32(sWh), sWlB = smem_u32(sWl);

  float acc[4][4][4];
#pragma unroll
  for (int mt = 0; mt < 4; mt++)
#pragma unroll
    for (int nt = 0; nt < 4; nt++)
#pragma unroll
      for (int i = 0; i < 4; i++) acc[mt][nt][i] = 0.f;

  uint4 rAh[2], rAl[2], rWh[2], rWl[2];
  rAh[0] = *(const uint4*)(pAh);     rAh[1] = *(const uint4*)(pAh + 8);
  rAl[0] = *(const uint4*)(pAl);     rAl[1] = *(const uint4*)(pAl + 8);
  rWh[0] = *(const uint4*)(pWh);     rWh[1] = *(const uint4*)(pWh + 8);
  rWl[0] = *(const uint4*)(pWl);     rWl[1] = *(const uint4*)(pWl + 8);

  for (int c = 0; c < DIMM / KC; c++) {
    __syncthreads();
    *(uint4*)&sAh[soff]     = rAh[0];  *(uint4*)&sAh[soff + 8] = rAh[1];
    *(uint4*)&sAl[soff]     = rAl[0];  *(uint4*)&sAl[soff + 8] = rAl[1];
    *(uint4*)&sWh[soff]     = rWh[0];  *(uint4*)&sWh[soff + 8] = rWh[1];
    *(uint4*)&sWl[soff]     = rWl[0];  *(uint4*)&sWl[soff + 8] = rWl[1];
    if (c + 1 < DIMM / KC) {
      const int ko = (c + 1) * KC;
      rAh[0] = *(const uint4*)(pAh + ko);  rAh[1] = *(const uint4*)(pAh + ko + 8);
      rAl[0] = *(const uint4*)(pAl + ko);  rAl[1] = *(const uint4*)(pAl + ko + 8);
      rWh[0] = *(const uint4*)(pWh + ko);  rWh[1] = *(const uint4*)(pWh + ko + 8);
      rWl[0] = *(const uint4*)(pWl + ko);  rWl[1] = *(const uint4*)(pWl + ko + 8);
    }
    __syncthreads();

#pragma unroll
    for (int ks = 0; ks < KC; ks += 16) {
      uint32_t ah[4][4], al[4][4];
#pragma unroll
      for (int mt = 0; mt < 4; mt++) {
        uint32_t off = (uint32_t)(((arowb + mt * 16) * ASTR + ks + acols) * 2);
        ldsm4(ah[mt], sAhB + off);
        ldsm4(al[mt], sAlB + off);
      }
      uint32_t bh[4][2], bl[4][2];
#pragma unroll
      for (int np = 0; np < 2; np++) {
        uint32_t off = (uint32_t)(((browb + np * 16) * ASTR + ks + bcols) * 2);
        uint32_t t[4];
        ldsm4(t, sWhB + off);   // NON-trans: W rows are k-contiguous (col-major B)
        bh[2*np][0] = t[0]; bh[2*np][1] = t[1]; bh[2*np+1][0] = t[2]; bh[2*np+1][1] = t[3];
        ldsm4(t, sWlB + off);
        bl[2*np][0] = t[0]; bl[2*np][1] = t[1]; bl[2*np+1][0] = t[2]; bl[2*np+1][1] = t[3];
      }
#pragma unroll
      for (int mt = 0; mt < 4; mt++)
#pragma unroll
        for (int nt = 0; nt < 4; nt++) {
          mma16816(acc[mt][nt], ah[mt], bh[nt]);
          mma16816(acc[mt][nt], ah[mt], bl[nt]);
          mma16816(acc[mt][nt], al[mt], bh[nt]);
        }
    }
  }

  const int lr = lane >> 2;
  const int lc = (lane & 3) << 1;
#pragma unroll
  for (int mt = 0; mt < 4; mt++) {
    const int row0 = m0 + warp_m * 64 + mt * 16 + lr;
#pragma unroll
    for (int nt = 0; nt < 4; nt++) {
      const int col = n0 + warp_n * 32 + nt * 8 + lc;
      const float b0 = bias[col], b1 = bias[col + 1];
      float v0 = acc[mt][nt][0] + b0;
      float v1 = acc[mt][nt][1] + b1;
      float v2 = acc[mt][nt][2] + b0;
      float v3 = acc[mt][nt][3] + b1;
      if (doSilu) { v0 = siluf(v0); v1 = siluf(v1); v2 = siluf(v2); v3 = siluf(v3); }
      *(float2*)(C + (size_t)row0 * DIMM + col)       = make_float2(v0, v1);
      *(float2*)(C + (size_t)(row0 + 8) * DIMM + col) = make_float2(v2, v3);
    }
  }
}

// merged QKV GEMM: grid (8, 128, 3); z selects W slab / bias / output
__global__ __launch_bounds__(256, 1) void gemm_qkv(
    const __nv_bfloat16* __restrict__ Ahi, const __nv_bfloat16* __restrict__ Alo,
    const __nv_bfloat16* __restrict__ Wh3, const __nv_bfloat16* __restrict__ Wl3,
    const float* __restrict__ bq, const float* __restrict__ bk, const float* __restrict__ bv,
    float* __restrict__ Cq, float* __restrict__ Ck, float* __restrict__ Cv)
{
  const int z = blockIdx.z;
  const __nv_bfloat16* Wh = Wh3 + (size_t)z * DIMM * DIMM;
  const __nv_bfloat16* Wl = Wl3 + (size_t)z * DIMM * DIMM;
  const float* bias = (z == 0) ? bq : ((z == 1) ? bk : bv);
  float* C = (z == 0) ? Cq : ((z == 1) ? Ck : Cv);
  gemm_body(Ahi, Alo, Wh, Wl, bias, C, 1, blockIdx.y << 7, blockIdx.x << 7);
}

__global__ __launch_bounds__(256, 1) void gemm_mma(
    const __nv_bfloat16* __restrict__ Ahi, const __nv_bfloat16* __restrict__ Alo,
    const __nv_bfloat16* __restrict__ Whi, const __nv_bfloat16* __restrict__ Wlo,
    const float* __restrict__ bias, float* __restrict__ C, int doSilu)
{
  gemm_body(Ahi, Alo, Whi, Wlo, bias, C, doSilu, blockIdx.y << 7, blockIdx.x << 7);
}

// ---------------- gate projections ----------------
__global__ __launch_bounds__(256) void gate_gemm(
    const float* __restrict__ X, const float* __restrict__ Wa, const float* __restrict__ ba,
    const float* __restrict__ Wb, const float* __restrict__ bbias,
    float* __restrict__ Ga, float* __restrict__ Gb)
{
  __shared__ float Xs[32][129];
  __shared__ float Ws[32][33];
  const int tid = threadIdx.x;
  const int m0  = blockIdx.x << 7;
  const int tm0 = (tid >> 4) << 3;
  const int tn0 = (tid & 15) << 1;

  float acc[8][2];
#pragma unroll
  for (int i = 0; i < 8; i++) { acc[i][0] = 0.f; acc[i][1] = 0.f; }

  for (int k0 = 0; k0 < 1024; k0 += 32) {
    __syncthreads();
#pragma unroll
    for (int ii = 0; ii < 4; ii++) {
      int idx = tid + (ii << 8);
      int rr = idx >> 3, c4 = (idx & 7) << 2;
      float4 v = *(const float4*)&X[(size_t)(m0 + rr) * DIMM + k0 + c4];
      Xs[c4+0][rr] = v.x; Xs[c4+1][rr] = v.y; Xs[c4+2][rr] = v.z; Xs[c4+3][rr] = v.w;
    }
    {
      int n = tid >> 3, c4 = (tid & 7) << 2;
      if (n < 32) {
        const float* wp = (n < 16) ? (Wa + (size_t)n * DIMM) : (Wb + (size_t)(n - 16) * DIMM);
        float4 v = *(const float4*)&wp[k0 + c4];
        Ws[c4+0][n] = v.x; Ws[c4+1][n] = v.y; Ws[c4+2][n] = v.z; Ws[c4+3][n] = v.w;
      }
    }
    __syncthreads();
#pragma unroll
    for (int kk = 0; kk < 32; kk++) {
      float wf0 = Ws[kk][tn0], wf1 = Ws[kk][tn0 + 1];
#pragma unroll
      for (int i = 0; i < 8; i++) {
        float av = Xs[kk][tm0 + i];
        acc[i][0] = fmaf(av, wf0, acc[i][0]);
        acc[i][1] = fmaf(av, wf1, acc[i][1]);
      }
    }
  }
#pragma unroll
  for (int j = 0; j < 2; j++) {
    int col = tn0 + j;
    float bi = (col < 16) ? ba[col] : bbias[col - 16];
    float* dst = (col < 16) ? Ga : Gb;
    int cc = col & 15;
#pragma unroll
    for (int i = 0; i < 8; i++) {
      int row = m0 + tm0 + i;
      dst[(size_t)row * 16 + cc] = sigmf(acc[i][j] + bi);
    }
  }
}

// ---------------- depthwise conv (K=4) + silu ----------------
__global__ __launch_bounds__(256) void conv_silu_kernel(
    const float* __restrict__ P, const float* __restrict__ wc, float* __restrict__ Y)
{
  const int c  = (blockIdx.x << 8) + threadIdx.x;
  const int b  = blockIdx.z;
  const int t0 = blockIdx.y << 7;
  const float w0 = wc[c*4+0], w1 = wc[c*4+1], w2 = wc[c*4+2], w3 = wc[c*4+3];
  const float* base  = P + (size_t)b * NN * DIMM + c;
  float*       ybase = Y + (size_t)b * NN * DIMM + c;
  float xm2 = (t0 >= 2) ? base[(size_t)(t0-2)*DIMM] : 0.f;
  float xm1 = (t0 >= 1) ? base[(size_t)(t0-1)*DIMM] : 0.f;
  float x0  = base[(size_t)t0 * DIMM];
#pragma unroll 4
  for (int t = t0; t < t0 + 128; t++) {
    float xp1 = (t + 1 < NN) ? base[(size_t)(t+1)*DIMM] : 0.f;
    float y = w0*xm2 + w1*xm1 + w2*x0 + w3*xp1;
    ybase[(size_t)t * DIMM] = siluf(y);
    xm2 = xm1; xm1 = x0; x0 = xp1;
  }
}

// ---------------- row l2norm (in place) ----------------
__global__ __launch_bounds__(256) void l2norm_kernel(float* __restrict__ X)
{
  __shared__ float red[8];
  float4* p = (float4*)(X + (size_t)blockIdx.x * DIMM);
  const int tid = threadIdx.x;
  float4 v = p[tid];
  float s = v.x*v.x + v.y*v.y + v.z*v.z + v.w*v.w;
#pragma unroll
  for (int o = 16; o > 0; o >>= 1) s += __shfl_xor_sync(0xffffffffu, s, o);
  if ((tid & 31) == 0) red[tid >> 5] = s;
  __syncthreads();
  float tot = red[0]+red[1]+red[2]+red[3]+red[4]+red[5]+red[6]+red[7];
  float inv = 1.f / (sqrtf(tot) + 1e-6f);
  v.x *= inv; v.y *= inv; v.z *= inv; v.w *= inv;
  p[tid] = v;
}

// ---------------- gated delta-rule scan (v2: deferred output reduction) -------
// Per step: 3 barriers (was 4). Output partials buffered per chunk, reduced
// once per chunk with coalesced stores.
__global__ __launch_bounds__(256) void scan_kernel(
    const float* __restrict__ Q, const float* __restrict__ Kv, const float* __restrict__ V,
    const float* __restrict__ A, const float* __restrict__ Bg, float* __restrict__ O)
{
  __shared__ float shq[CH][64], shk[CH][64], shv[CH][64];
  __shared__ float sha[CH], shb[CH];
  __shared__ float mat[64][68];
  __shared__ float part[64][4];
  __shared__ float coefsh[64];
  __shared__ float obuf[CH][64][4];
  const int tid = threadIdx.x;
  const int e = tid & 63, g = tid >> 6;
  const int bh = blockIdx.x;
  const int b = bh >> 4, h = bh & 15;
  const size_t base = ((size_t)b * NN) * DIMM + h * 64;
  float S[16];
#pragma unroll
  for (int i = 0; i < 16; i++) S[i] = 0.f;

  for (int t0 = 0; t0 < NN; t0 += CH) {
    __syncthreads();
    for (int idx = tid; idx < CH*64; idx += 256) {
      int i = idx >> 6, ee = idx & 63;
      size_t off = base + (size_t)(t0 + i) * DIMM + ee;
      shq[i][ee] = Q[off]; shk[i][ee] = Kv[off]; shv[i][ee] = V[off];
    }
    if (tid < CH) {
      size_t off = ((size_t)b * NN + t0 + tid) * 16 + h;
      sha[tid] = A[off]; shb[tid] = Bg[off];
    }
    __syncthreads();

    for (int i = 0; i < CH; i++) {
      const float ke = shk[i][e];
      const float aT = sha[i], bT = shb[i];
#pragma unroll
      for (int j = 0; j < 16; j++) mat[16*g + j][e] = S[j] * ke;
      __syncthreads();
      const float4* rp = (const float4*)&mat[e][16*g];
      float4 p0 = rp[0], p1 = rp[1], p2 = rp[2], p3 = rp[3];
      part[e][g] = (p0.x+p0.y+p0.z+p0.w) + (p1.x+p1.y+p1.z+p1.w)
                 + (p2.x+p2.y+p2.z+p2.w) + (p3.x+p3.y+p3.z+p3.w);
      __syncthreads();
      if (g == 0) {
        float4 pr = *(const float4*)&part[e][0];
        float Sk = pr.x + pr.y + pr.z + pr.w;
        coefsh[e] = bT * (shv[i][e] - aT * Sk);
      }
      __syncthreads();
      float op = 0.f;
#pragma unroll
      for (int j4 = 0; j4 < 4; j4++) {
        float4 cf = *(const float4*)&coefsh[16*g + 4*j4];
        float4 qv = *(const float4*)&shq[i][16*g + 4*j4];
        int j = 4*j4;
        S[j+0] = aT*S[j+0] + cf.x*ke; op = fmaf(qv.x, S[j+0], op);
        S[j+1] = aT*S[j+1] + cf.y*ke; op = fmaf(qv.y, S[j+1], op);
        S[j+2] = aT*S[j+2] + cf.z*ke; op = fmaf(qv.z, S[j+2], op);
        S[j+3] = aT*S[j+3] + cf.w*ke; op = fmaf(qv.w, S[j+3], op);
      }
      obuf[i][e][g] = op;           // deferred reduction; no barrier here
    }
    __syncthreads();                 // obuf complete
#pragma unroll
    for (int p = 0; p < (CH*64)/256; p++) {
      int idx = tid + (p << 8);
      int i = idx >> 6, ee = idx & 63;
      float4 pr = *(const float4*)&obuf[i][ee][0];
      O[base + (size_t)(t0 + i) * DIMM + ee] = pr.x + pr.y + pr.z + pr.w;
    }
  }
}

// ---------------- launch ----------------
extern "C" void kernel_launch(void* const* d_in, const int* in_sizes, int n_in,
                              void* d_out, int out_size) {
  const float* x      = (const float*)d_in[0];
  const float* Wq     = (const float*)d_in[1];
  const float* bq     = (const float*)d_in[2];
  const float* Wk     = (const float*)d_in[3];
  const float* bk     = (const float*)d_in[4];
  const float* Wv     = (const float*)d_in[5];
  const float* bv     = (const float*)d_in[6];
  const float* Wa     = (const float*)d_in[7];
  const float* ba     = (const float*)d_in[8];
  const float* Wb     = (const float*)d_in[9];
  const float* bb     = (const float*)d_in[10];
  const float* conv_q = (const float*)d_in[11];
  const float* conv_k = (const float*)d_in[12];
  const float* conv_v = (const float*)d_in[13];
  const float* Wo     = (const float*)d_in[14];
  const float* bo     = (const float*)d_in[15];
  float* out = (float*)d_out;

  void *pq, *pk, *pv, *q, *k, *v, *o, *ga, *gb;
  void *xhi, *xlo, *ohi, *olo, *w3hi, *w3lo, *wohi, *wolo;
  cudaGetSymbolAddress(&pq, g_pq);
  cudaGetSymbolAddress(&pk, g_pk);
  cudaGetSymbolAddress(&pv, g_pv);
  cudaGetSymbolAddress(&q,  g_q);
  cudaGetSymbolAddress(&v,  g_v);
  cudaGetSymbolAddress(&k,  g_k);
  cudaGetSymbolAddress(&o,  g_o);
  cudaGetSymbolAddress(&ga, g_a);
  cudaGetSymbolAddress(&gb, g_b);
  cudaGetSymbolAddress(&xhi, g_xhi);
  cudaGetSymbolAddress(&xlo, g_xlo);
  cudaGetSymbolAddress(&ohi, g_ohi);
  cudaGetSymbolAddress(&olo, g_olo);
  cudaGetSymbolAddress(&w3hi, g_w3hi);
  cudaGetSymbolAddress(&w3lo, g_w3lo);
  cudaGetSymbolAddress(&wohi, g_wohi);
  cudaGetSymbolAddress(&wolo, g_wolo);

  const int NW4 = (DIMM * DIMM) / 4;
  const int NX4 = (MM * DIMM) / 4;
  const size_t WSLAB = (size_t)DIMM * DIMM;

  // launches 1-5: splits (so launch #6 = gemm_qkv for ncu -s 5 -c 1)
  split_kernel<<<(NX4 + 255) / 256, 256>>>(x, (__nv_bfloat16*)xhi, (__nv_bfloat16*)xlo, NX4);
  split_kernel<<<(NW4 + 255) / 256, 256>>>(Wq, (__nv_bfloat16*)w3hi,          (__nv_bfloat16*)w3lo,          NW4);
  split_kernel<<<(NW4 + 255) / 256, 256>>>(Wk, (__nv_bfloat16*)w3hi + WSLAB,  (__nv_bfloat16*)w3lo + WSLAB,  NW4);
  split_kernel<<<(NW4 + 255) / 256, 256>>>(Wv, (__nv_bfloat16*)w3hi + 2*WSLAB,(__nv_bfloat16*)w3lo + 2*WSLAB,NW4);
  split_kernel<<<(NW4 + 255) / 256, 256>>>(Wo, (__nv_bfloat16*)wohi, (__nv_bfloat16*)wolo, NW4);

  dim3 qkvgrid(8, MM / 128, 3);
  gemm_qkv<<<qkvgrid, 256>>>((const __nv_bfloat16*)xhi, (const __nv_bfloat16*)xlo,
                             (const __nv_bfloat16*)w3hi, (const __nv_bfloat16*)w3lo,
                             bq, bk, bv, (float*)pq, (float*)pk, (float*)pv);

  gate_gemm<<<MM / 128, 256>>>(x, Wa, ba, Wb, bb, (float*)ga, (float*)gb);

  dim3 cgrid(DIMM / 256, NN / 128, BB);
  conv_silu_kernel<<<cgrid, 256>>>((const float*)pq, conv_q, (float*)q);
  conv_silu_kernel<<<cgrid, 256>>>((const float*)pk, conv_k, (float*)k);
  conv_silu_kernel<<<cgrid, 256>>>((const float*)pv, conv_v, (float*)v);

  l2norm_kernel<<<MM, 256>>>((float*)q);
  l2norm_kernel<<<MM, 256>>>((float*)k);

  scan_kernel<<<BB * HH, 256>>>((const float*)q, (const float*)k, (const float*)v,
                                (const float*)ga, (const float*)gb, (float*)o);

  split_kernel<<<(NX4 + 255) / 256, 256>>>((const float*)o, (__nv_bfloat16*)ohi, (__nv_bfloat16*)olo, NX4);
  dim3 ggrid(8, MM / 128);
  gemm_mma<<<ggrid, 256>>>((const __nv_bfloat16*)ohi, (const __nv_bfloat16*)olo,
                           (const __nv_bfloat16*)wohi, (const __nv_bfloat16*)wolo,
                           bo, out, 0);
}

// round 11
// speedup vs baseline: 1.0087x; 1.0087x over previous
#include <cuda_runtime.h>
#include <cuda_bf16.h>
#include <math.h>
#include <stdint.h>

#define BB   8
#define NN   2048
#define DIMM 1024
#define HH   16
#define MM   (BB*NN)   /* 16384 rows */

// ---------------- scratch (static device globals; no allocation) ----------------
__device__ float g_pq[(size_t)MM*DIMM];
__device__ float g_pk[(size_t)MM*DIMM];
__device__ float g_pv[(size_t)MM*DIMM];
__device__ float g_q [(size_t)MM*DIMM];
__device__ float g_k [(size_t)MM*DIMM];
__device__ float g_v [(size_t)MM*DIMM];
__device__ float g_o [(size_t)MM*DIMM];
__device__ float g_a [(size_t)MM*HH];
__device__ float g_b [(size_t)MM*HH];
__device__ __align__(256) __nv_bfloat16 g_xhi[(size_t)MM*DIMM];
__device__ __align__(256) __nv_bfloat16 g_xlo[(size_t)MM*DIMM];
__device__ __align__(256) __nv_bfloat16 g_ohi[(size_t)MM*DIMM];
__device__ __align__(256) __nv_bfloat16 g_olo[(size_t)MM*DIMM];
__device__ __align__(256) __nv_bfloat16 g_w3hi[(size_t)3*DIMM*DIMM];
__device__ __align__(256) __nv_bfloat16 g_w3lo[(size_t)3*DIMM*DIMM];
__device__ __align__(256) __nv_bfloat16 g_wohi[(size_t)DIMM*DIMM];
__device__ __align__(256) __nv_bfloat16 g_wolo[(size_t)DIMM*DIMM];

// ---------------- helpers ----------------
__device__ __forceinline__ float siluf(float x){ return x / (1.f + __expf(-x)); }
__device__ __forceinline__ float sigmf(float x){ return 1.f / (1.f + __expf(-x)); }

__device__ __forceinline__ uint32_t smem_u32(const void* p){
  uint32_t a;
  asm("{ .reg .u64 t; cvta.to.shared.u64 t, %1; cvt.u32.u64 %0, t; }" : "=r"(a) : "l"(p));
  return a;
}
__device__ __forceinline__ void ldsm4(uint32_t* d, uint32_t addr){
  asm volatile("ldmatrix.sync.aligned.m8n8.x4.shared.b16 {%0,%1,%2,%3}, [%4];"
    : "=r"(d[0]),"=r"(d[1]),"=r"(d[2]),"=r"(d[3]) : "r"(addr));
}
__device__ __forceinline__ void mma16816(float* d, const uint32_t* a, const uint32_t* b){
  asm volatile("mma.sync.aligned.m16n8k16.row.col.f32.bf16.bf16.f32 "
    "{%0,%1,%2,%3}, {%4,%5,%6,%7}, {%8,%9}, {%0,%1,%2,%3};"
    : "+f"(d[0]),"+f"(d[1]),"+f"(d[2]),"+f"(d[3])
    : "r"(a[0]),"r"(a[1]),"r"(a[2]),"r"(a[3]), "r"(b[0]),"r"(b[1]));
}

// ---------------- bf16 hi/lo split ----------------
__global__ __launch_bounds__(256) void split_kernel(
    const float* __restrict__ X, __nv_bfloat16* __restrict__ Hp, __nv_bfloat16* __restrict__ Lp, int n4)
{
  int i = blockIdx.x * 256 + threadIdx.x;
  if (i >= n4) return;
  float4 v = ((const float4*)X)[i];
  __nv_bfloat16 h0 = __float2bfloat16(v.x), h1 = __float2bfloat16(v.y);
  __nv_bfloat16 h2 = __float2bfloat16(v.z), h3 = __float2bfloat16(v.w);
  __nv_bfloat16 l0 = __float2bfloat16(v.x - __bfloat162float(h0));
  __nv_bfloat16 l1 = __float2bfloat16(v.y - __bfloat162float(h1));
  __nv_bfloat16 l2 = __float2bfloat16(v.z - __bfloat162float(h2));
  __nv_bfloat16 l3 = __float2bfloat16(v.w - __bfloat162float(h3));
  __nv_bfloat162* Hq = (__nv_bfloat162*)Hp;
  __nv_bfloat162* Lq = (__nv_bfloat162*)Lp;
  Hq[2*i]   = __nv_bfloat162(h0, h1);
  Hq[2*i+1] = __nv_bfloat162(h2, h3);
  Lq[2*i]   = __nv_bfloat162(l0, l1);
  Lq[2*i+1] = __nv_bfloat162(l2, l3);
}

// ---------------- HMMA bf16-split GEMM body ----------------
#define KC 32
#define ASTR 40          /* bf16 row stride (80 B, 16B-mult, conflict-free) */

__device__ __forceinline__ void gemm_body(
    const __nv_bfloat16* __restrict__ Ahi, const __nv_bfloat16* __restrict__ Alo,
    const __nv_bfloat16* __restrict__ Whi, const __nv_bfloat16* __restrict__ Wlo,
    const float* __restrict__ bias, float* __restrict__ C, int doSilu,
    int m0, int n0)
{
  __shared__ __nv_bfloat16 sAh[128*ASTR], sAl[128*ASTR], sWh[128*ASTR], sWl[128*ASTR];

  const int tid  = threadIdx.x;
  const int w    = tid >> 5;
  const int lane = tid & 31;
  const int warp_m = w >> 2;
  const int warp_n = w & 3;

  const int r    = tid >> 1;
  const int gcol = (tid & 1) << 4;
  const __nv_bfloat16* pAh = Ahi + (size_t)(m0 + r) * DIMM + gcol;
  const __nv_bfloat16* pAl = Alo + (size_t)(m0 + r) * DIMM + gcol;
  const __nv_bfloat16* pWh = Whi + (size_t)(n0 + r) * DIMM + gcol;
  const __nv_bfloat16* pWl = Wlo + (size_t)(n0 + r) * DIMM + gcol;
  const int soff = r * ASTR + gcol;

  const int mmat = lane >> 3, rr = lane & 7;
  const int arowb = warp_m * 64 + ((mmat & 1) << 3) + rr;
  const int acols = (mmat >> 1) << 3;
  const int browb = warp_n * 32 + ((mmat >> 1) << 3) + rr;
  const int bcols = (mmat & 1) << 3;
  const uint32_t sAhB = smem_u32(sAh), sAlB = smem_u32(sAl);
  const uint32_t sWhB = smem_u32(sWh), sWlB = smem_u32(sWl);

  float acc[4][4][4];
#pragma unroll
  for (int mt = 0; mt < 4; mt++)
#pragma unroll
    for (int nt = 0; nt < 4; nt++)
#pragma unroll
      for (int i = 0; i < 4; i++) acc[mt][nt][i] = 0.f;

  uint4 rAh[2], rAl[2], rWh[2], rWl[2];
  rAh[0] = *(const uint4*)(pAh);     rAh[1] = *(const uint4*)(pAh + 8);
  rAl[0] = *(const uint4*)(pAl);     rAl[1] = *(const uint4*)(pAl + 8);
  rWh[0] = *(const uint4*)(pWh);     rWh[1] = *(const uint4*)(pWh + 8);
  rWl[0] = *(const uint4*)(pWl);     rWl[1] = *(const uint4*)(pWl + 8);

  for (int c = 0; c < DIMM / KC; c++) {
    __syncthreads();
    *(uint4*)&sAh[soff]     = rAh[0];  *(uint4*)&sAh[soff + 8] = rAh[1];
    *(uint4*)&sAl[soff]     = rAl[0];  *(uint4*)&sAl[soff + 8] = rAl[1];
    *(uint4*)&sWh[soff]     = rWh[0];  *(uint4*)&sWh[soff + 8] = rWh[1];
    *(uint4*)&sWl[soff]     = rWl[0];  *(uint4*)&sWl[soff + 8] = rWl[1];
    if (c + 1 < DIMM / KC) {
      const int ko = (c + 1) * KC;
      rAh[0] = *(const uint4*)(pAh + ko);  rAh[1] = *(const uint4*)(pAh + ko + 8);
      rAl[0] = *(const uint4*)(pAl + ko);  rAl[1] = *(const uint4*)(pAl + ko + 8);
      rWh[0] = *(const uint4*)(pWh + ko);  rWh[1] = *(const uint4*)(pWh + ko + 8);
      rWl[0] = *(const uint4*)(pWl + ko);  rWl[1] = *(const uint4*)(pWl + ko + 8);
    }
    __syncthreads();

#pragma unroll
    for (int ks = 0; ks < KC; ks += 16) {
      uint32_t ah[4][4], al[4][4];
#pragma unroll
      for (int mt = 0; mt < 4; mt++) {
        uint32_t off = (uint32_t)(((arowb + mt * 16) * ASTR + ks + acols) * 2);
        ldsm4(ah[mt], sAhB + off);
        ldsm4(al[mt], sAlB + off);
      }
      uint32_t bh[4][2], bl[4][2];
#pragma unroll
      for (int np = 0; np < 2; np++) {
        uint32_t off = (uint32_t)(((browb + np * 16) * ASTR + ks + bcols) * 2);
        uint32_t t[4];
        ldsm4(t, sWhB + off);
        bh[2*np][0] = t[0]; bh[2*np][1] = t[1]; bh[2*np+1][0] = t[2]; bh[2*np+1][1] = t[3];
        ldsm4(t, sWlB + off);
        bl[2*np][0] = t[0]; bl[2*np][1] = t[1]; bl[2*np+1][0] = t[2]; bl[2*np+1][1] = t[3];
      }
#pragma unroll
      for (int mt = 0; mt < 4; mt++)
#pragma unroll
        for (int nt = 0; nt < 4; nt++) {
          mma16816(acc[mt][nt], ah[mt], bh[nt]);
          mma16816(acc[mt][nt], ah[mt], bl[nt]);
          mma16816(acc[mt][nt], al[mt], bh[nt]);
        }
    }
  }

  const int lr = lane >> 2;
  const int lc = (lane & 3) << 1;
#pragma unroll
  for (int mt = 0; mt < 4; mt++) {
    const int row0 = m0 + warp_m * 64 + mt * 16 + lr;
#pragma unroll
    for (int nt = 0; nt < 4; nt++) {
      const int col = n0 + warp_n * 32 + nt * 8 + lc;
      const float b0 = bias[col], b1 = bias[col + 1];
      float v0 = acc[mt][nt][0] + b0;
      float v1 = acc[mt][nt][1] + b1;
      float v2 = acc[mt][nt][2] + b0;
      float v3 = acc[mt][nt][3] + b1;
      if (doSilu) { v0 = siluf(v0); v1 = siluf(v1); v2 = siluf(v2); v3 = siluf(v3); }
      *(float2*)(C + (size_t)row0 * DIMM + col)       = make_float2(v0, v1);
      *(float2*)(C + (size_t)(row0 + 8) * DIMM + col) = make_float2(v2, v3);
    }
  }
}

__global__ __launch_bounds__(256, 1) void gemm_qkv(
    const __nv_bfloat16* __restrict__ Ahi, const __nv_bfloat16* __restrict__ Alo,
    const __nv_bfloat16* __restrict__ Wh3, const __nv_bfloat16* __restrict__ Wl3,
    const float* __restrict__ bq, const float* __restrict__ bk, const float* __restrict__ bv,
    float* __restrict__ Cq, float* __restrict__ Ck, float* __restrict__ Cv)
{
  const int z = blockIdx.z;
  const __nv_bfloat16* Wh = Wh3 + (size_t)z * DIMM * DIMM;
  const __nv_bfloat16* Wl = Wl3 + (size_t)z * DIMM * DIMM;
  const float* bias = (z == 0) ? bq : ((z == 1) ? bk : bv);
  float* C = (z == 0) ? Cq : ((z == 1) ? Ck : Cv);
  gemm_body(Ahi, Alo, Wh, Wl, bias, C, 1, blockIdx.y << 7, blockIdx.x << 7);
}

__global__ __launch_bounds__(256, 1) void gemm_mma(
    const __nv_bfloat16* __restrict__ Ahi, const __nv_bfloat16* __restrict__ Alo,
    const __nv_bfloat16* __restrict__ Whi, const __nv_bfloat16* __restrict__ Wlo,
    const float* __restrict__ bias, float* __restrict__ C, int doSilu)
{
  gemm_body(Ahi, Alo, Whi, Wlo, bias, C, doSilu, blockIdx.y << 7, blockIdx.x << 7);
}

// ---------------- gate projections ----------------
__global__ __launch_bounds__(256) void gate_gemm(
    const float* __restrict__ X, const float* __restrict__ Wa, const float* __restrict__ ba,
    const float* __restrict__ Wb, const float* __restrict__ bbias,
    float* __restrict__ Ga, float* __restrict__ Gb)
{
  __shared__ float Xs[32][129];
  __shared__ float Ws[32][33];
  const int tid = threadIdx.x;
  const int m0  = blockIdx.x << 7;
  const int tm0 = (tid >> 4) << 3;
  const int tn0 = (tid & 15) << 1;

  float acc[8][2];
#pragma unroll
  for (int i = 0; i < 8; i++) { acc[i][0] = 0.f; acc[i][1] = 0.f; }

  for (int k0 = 0; k0 < 1024; k0 += 32) {
    __syncthreads();
#pragma unroll
    for (int ii = 0; ii < 4; ii++) {
      int idx = tid + (ii << 8);
      int rr = idx >> 3, c4 = (idx & 7) << 2;
      float4 v = *(const float4*)&X[(size_t)(m0 + rr) * DIMM + k0 + c4];
      Xs[c4+0][rr] = v.x; Xs[c4+1][rr] = v.y; Xs[c4+2][rr] = v.z; Xs[c4+3][rr] = v.w;
    }
    {
      int n = tid >> 3, c4 = (tid & 7) << 2;
      if (n < 32) {
        const float* wp = (n < 16) ? (Wa + (size_t)n * DIMM) : (Wb + (size_t)(n - 16) * DIMM);
        float4 v = *(const float4*)&wp[k0 + c4];
        Ws[c4+0][n] = v.x; Ws[c4+1][n] = v.y; Ws[c4+2][n] = v.z; Ws[c4+3][n] = v.w;
      }
    }
    __syncthreads();
#pragma unroll
    for (int kk = 0; kk < 32; kk++) {
      float wf0 = Ws[kk][tn0], wf1 = Ws[kk][tn0 + 1];
#pragma unroll
      for (int i = 0; i < 8; i++) {
        float av = Xs[kk][tm0 + i];
        acc[i][0] = fmaf(av, wf0, acc[i][0]);
        acc[i][1] = fmaf(av, wf1, acc[i][1]);
      }
    }
  }
#pragma unroll
  for (int j = 0; j < 2; j++) {
    int col = tn0 + j;
    float bi = (col < 16) ? ba[col] : bbias[col - 16];
    float* dst = (col < 16) ? Ga : Gb;
    int cc = col & 15;
#pragma unroll
    for (int i = 0; i < 8; i++) {
      int row = m0 + tm0 + i;
      dst[(size_t)row * 16 + cc] = sigmf(acc[i][j] + bi);
    }
  }
}

// ---------------- depthwise conv (K=4) + silu ----------------
__global__ __launch_bounds__(256) void conv_silu_kernel(
    const float* __restrict__ P, const float* __restrict__ wc, float* __restrict__ Y)
{
  const int c  = (blockIdx.x << 8) + threadIdx.x;
  const int b  = blockIdx.z;
  const int t0 = blockIdx.y << 7;
  const float w0 = wc[c*4+0], w1 = wc[c*4+1], w2 = wc[c*4+2], w3 = wc[c*4+3];
  const float* base  = P + (size_t)b * NN * DIMM + c;
  float*       ybase = Y + (size_t)b * NN * DIMM + c;
  float xm2 = (t0 >= 2) ? base[(size_t)(t0-2)*DIMM] : 0.f;
  float xm1 = (t0 >= 1) ? base[(size_t)(t0-1)*DIMM] : 0.f;
  float x0  = base[(size_t)t0 * DIMM];
#pragma unroll 4
  for (int t = t0; t < t0 + 128; t++) {
    float xp1 = (t + 1 < NN) ? base[(size_t)(t+1)*DIMM] : 0.f;
    float y = w0*xm2 + w1*xm1 + w2*x0 + w3*xp1;
    ybase[(size_t)t * DIMM] = siluf(y);
    xm2 = xm1; xm1 = x0; x0 = xp1;
  }
}

// ---------------- row l2norm (in place) ----------------
__global__ __launch_bounds__(256) void l2norm_kernel(float* __restrict__ X)
{
  __shared__ float red[8];
  float4* p = (float4*)(X + (size_t)blockIdx.x * DIMM);
  const int tid = threadIdx.x;
  float4 v = p[tid];
  float s = v.x*v.x + v.y*v.y + v.z*v.z + v.w*v.w;
#pragma unroll
  for (int o = 16; o > 0; o >>= 1) s += __shfl_xor_sync(0xffffffffu, s, o);
  if ((tid & 31) == 0) red[tid >> 5] = s;
  __syncthreads();
  float tot = red[0]+red[1]+red[2]+red[3]+red[4]+red[5]+red[6]+red[7];
  float inv = 1.f / (sqrtf(tot) + 1e-6f);
  v.x *= inv; v.y *= inv; v.z *= inv; v.w *= inv;
  p[tid] = v;
}

// ---------------- chunked gated delta-rule scan (exact WY/UT form) ------------
// One CTA per (b,h); 512 threads; chunk L=32; S and S^T both kept in smem.
// Recurrence: S_t = a_t S_{t-1} + w_t k_t^T, w_t = b_t(v_t - a_t S_{t-1} k_t).
// Per chunk:  D[t][s] = prod_{s<r<=t} a_r (exact), Acum[t] = prod_{0..t} a_r.
//   Y0[t][d] = (S0 k_t)[d];  Gb[s][t] = b_t D[t][s] (k_s.k_t)   (s<t)
//   solve: w_t = b_t(v_t - Acum_t Y0_t) - sum_{s<t} Gb[s][t] w_s
//   Z0[t][e] = (S0^T q_t)[e];  Hm[t][s] = D[t][s] (q_t.w_s)  (s<=t, D[t][t]=1)
//   o_t[e] = Acum_t Z0[t][e] + sum_{s<=t} Hm[t][s] k_s[e]
//   S <- Acum_31 S + sum_s D[31][s] w_s k_s^T  (and same for S^T)
#define SPAD 68
#define SCAN_FLOATS (4352*2 + 2176*5 + 1056*3 + 96)
#define SCAN_SMEM   (SCAN_FLOATS*4)

__global__ __launch_bounds__(512, 1) void scan_kernel(
    const float* __restrict__ Qg, const float* __restrict__ Kg, const float* __restrict__ Vg,
    const float* __restrict__ Ag, const float* __restrict__ Bgg, float* __restrict__ Og)
{
  extern __shared__ float sm[];
  float* S   = sm;                 // [64][68]
  float* T   = sm + 4352;         // S^T [64][68]  (T[e][d])
  float* q   = sm + 8704;         // [32][68]
  float* kkk = sm + 10880;        // [32][68]
  float* vvv = sm + 13056;        // [32][68]
  float* W   = sm + 15232;        // [32][68]  (w_t rows over d)
  float* YZ  = sm + 17408;        // [32][68]  Y0 then Z0
  float* D   = sm + 19584;        // [32][33]
  float* Gb  = sm + 20640;        // [32][33]  (b_t D G, indexed [s][t])
  float* Hm  = sm + 21696;        // [32][33]  ([t][s])
  float* aa  = sm + 22752;        // [32]
  float* bb  = sm + 22784;        // [32]
  float* Ac  = sm + 22816;        // [32]

  const int tid = threadIdx.x;
  const int bh = blockIdx.x;
  const int b = bh >> 4, h = bh & 15;
  const size_t base = ((size_t)b * NN) * DIMM + h * 64;

  for (int i = tid; i < 4352*2; i += 512) sm[i] = 0.f;
  __syncthreads();

  for (int t0 = 0; t0 < NN; t0 += 32) {
    // ---- load chunk ----
#pragma unroll
    for (int j = 0; j < 4; j++) {
      int idx = tid + (j << 9);
      int t = idx >> 6, e = idx & 63;
      size_t off = base + (size_t)(t0 + t) * DIMM + e;
      q[t*SPAD+e] = Qg[off]; kkk[t*SPAD+e] = Kg[off]; vvv[t*SPAD+e] = Vg[off];
    }
    if (tid < 32) {
      size_t off = ((size_t)b * NN + t0 + tid) * 16 + h;
      aa[tid] = Ag[off]; bb[tid] = Bgg[off];
    }
    __syncthreads();

    // ---- D (warp0, lane = s) and Acum (independent per lane) ----
    if (tid < 32) {
      int s = tid;
      float d = 1.f;
      D[s*33 + s] = 1.f;
      for (int t = s + 1; t < 32; t++) { d *= aa[t]; D[t*33 + s] = d; }
      float p = 1.f;
      for (int r = 0; r <= s; r++) p *= aa[r];
      Ac[s] = p;
    }
    // ---- Y0[t][d] = sum_e k[t][e] * T[e][d] ----
    {
      int d = tid & 63, tb = tid >> 6;
      float acc0=0.f, acc1=0.f, acc2=0.f, acc3=0.f;
      for (int e = 0; e < 64; e++) {
        float tv = T[e*SPAD + d];
        acc0 = fmaf(kkk[(tb+ 0)*SPAD+e], tv, acc0);
        acc1 = fmaf(kkk[(tb+ 8)*SPAD+e], tv, acc1);
        acc2 = fmaf(kkk[(tb+16)*SPAD+e], tv, acc2);
        acc3 = fmaf(kkk[(tb+24)*SPAD+e], tv, acc3);
      }
      YZ[(tb+ 0)*SPAD+d] = acc0; YZ[(tb+ 8)*SPAD+d] = acc1;
      YZ[(tb+16)*SPAD+d] = acc2; YZ[(tb+24)*SPAD+d] = acc3;
    }
    __syncthreads();

    // ---- Gb[s][t] = b_t * D[t][s] * (k_s . k_t), s<t ----
#pragma unroll
    for (int j = 0; j < 2; j++) {
      int idx = tid + (j << 9);
      int s = idx >> 5, t = idx & 31;
      if (s < t) {
        const float4* ks = (const float4*)(kkk + s*SPAD);
        const float4* kt = (const float4*)(kkk + t*SPAD);
        float dot = 0.f;
#pragma unroll
        for (int e4 = 0; e4 < 16; e4++) {
          float4 x = ks[e4], y = kt[e4];
          dot += x.x*y.x + x.y*y.y + x.z*y.z + x.w*y.w;
        }
        Gb[s*33 + t] = bb[t] * D[t*33 + s] * dot;
      }
    }
    __syncthreads();

    // ---- triangular solve (64 threads, one per d) ----
    if (tid < 64) {
      int d = tid;
      float w[32];
#pragma unroll
      for (int t = 0; t < 32; t++) {
        float acc = 0.f;
#pragma unroll
        for (int s = 0; s < t; s++) acc = fmaf(Gb[s*33 + t], w[s], acc);
        w[t] = bb[t] * (vvv[t*SPAD + d] - Ac[t] * YZ[t*SPAD + d]) - acc;
        W[t*SPAD + d] = w[t];
      }
    }
    __syncthreads();

    // ---- Hm[t][s] = D[t][s]*(q_t.w_s), s<=t ; Z0[t][e] = sum_d q[t][d]S[d][e] ----
#pragma unroll
    for (int j = 0; j < 2; j++) {
      int idx = tid + (j << 9);
      int t = idx >> 5, s = idx & 31;
      if (s <= t) {
        const float4* qt = (const float4*)(q + t*SPAD);
        const float4* ws = (const float4*)(W + s*SPAD);
        float dot = 0.f;
#pragma unroll
        for (int d4 = 0; d4 < 16; d4++) {
          float4 x = qt[d4], y = ws[d4];
          dot += x.x*y.x + x.y*y.y + x.z*y.z + x.w*y.w;
        }
        Hm[t*33 + s] = D[t*33 + s] * dot;
      }
    }
    {
      int e = tid & 63, tb = tid >> 6;
      float acc0=0.f, acc1=0.f, acc2=0.f, acc3=0.f;
      for (int d = 0; d < 64; d++) {
        float sv = S[d*SPAD + e];
        acc0 = fmaf(q[(tb+ 0)*SPAD+d], sv, acc0);
        acc1 = fmaf(q[(tb+ 8)*SPAD+d], sv, acc1);
        acc2 = fmaf(q[(tb+16)*SPAD+d], sv, acc2);
        acc3 = fmaf(q[(tb+24)*SPAD+d], sv, acc3);
      }
      __syncthreads();   // Y0 fully consumed (solve done) before overwrite
      YZ[(tb+ 0)*SPAD+e] = acc0; YZ[(tb+ 8)*SPAD+e] = acc1;
      YZ[(tb+16)*SPAD+e] = acc2; YZ[(tb+24)*SPAD+e] = acc3;
    }
    __syncthreads();

    // ---- outputs + state update ----
    {
      int e = tid & 63, tb = tid >> 6;
#pragma unroll
      for (int j = 0; j < 4; j++) {
        int t = tb + (j << 3);
        float acc = Ac[t] * YZ[t*SPAD + e];
        for (int s = 0; s <= t; s++) acc = fmaf(Hm[t*33 + s], kkk[s*SPAD + e], acc);
        Og[base + (size_t)(t0 + t) * DIMM + e] = acc;
      }
    }
    {
      // S[d][e]: warp fixed d-group, lanes over e
      int e = tid & 63, db = tid >> 6;
      float acc[8];
#pragma unroll
      for (int j = 0; j < 8; j++) acc[j] = Ac[31] * S[(db + (j<<3))*SPAD + e];
      for (int s = 0; s < 32; s++) {
        float t1 = D[31*33 + s] * kkk[s*SPAD + e];
#pragma unroll
        for (int j = 0; j < 8; j++) acc[j] = fmaf(W[s*SPAD + db + (j<<3)], t1, acc[j]);
      }
#pragma unroll
      for (int j = 0; j < 8; j++) S[(db + (j<<3))*SPAD + e] = acc[j];
    }
    {
      // T[e][d]: warp fixed e-group, lanes over d
      int d = tid & 63, eb = tid >> 6;
      float acc[8];
#pragma unroll
      for (int j = 0; j < 8; j++) acc[j] = Ac[31] * T[(eb + (j<<3))*SPAD + d];
      for (int s = 0; s < 32; s++) {
        float t1 = D[31*33 + s] * W[s*SPAD + d];
#pragma unroll
        for (int j = 0; j < 8; j++) acc[j] = fmaf(kkk[s*SPAD + eb + (j<<3)], t1, acc[j]);
      }
#pragma unroll
      for (int j = 0; j < 8; j++) T[(eb + (j<<3))*SPAD + d] = acc[j];
    }
    __syncthreads();
  }
}

// ---------------- launch ----------------
extern "C" void kernel_launch(void* const* d_in, const int* in_sizes, int n_in,
                              void* d_out, int out_size) {
  const float* x      = (const float*)d_in[0];
  const float* Wq     = (const float*)d_in[1];
  const float* bq     = (const float*)d_in[2];
  const float* Wk     = (const float*)d_in[3];
  const float* bk     = (const float*)d_in[4];
  const float* Wv     = (const float*)d_in[5];
  const float* bv     = (const float*)d_in[6];
  const float* Wa     = (const float*)d_in[7];
  const float* ba     = (const float*)d_in[8];
  const float* Wb     = (const float*)d_in[9];
  const float* bb     = (const float*)d_in[10];
  const float* conv_q = (const float*)d_in[11];
  const float* conv_k = (const float*)d_in[12];
  const float* conv_v = (const float*)d_in[13];
  const float* Wo     = (const float*)d_in[14];
  const float* bo     = (const float*)d_in[15];
  float* out = (float*)d_out;

  void *pq, *pk, *pv, *qb, *kb, *vb, *ob, *ga, *gb;
  void *xhi, *xlo, *ohi, *olo, *w3hi, *w3lo, *wohi, *wolo;
  cudaGetSymbolAddress(&pq, g_pq);
  cudaGetSymbolAddress(&pk, g_pk);
  cudaGetSymbolAddress(&pv, g_pv);
  cudaGetSymbolAddress(&qb, g_q);
  cudaGetSymbolAddress(&vb, g_v);
  cudaGetSymbolAddress(&kb, g_k);
  cudaGetSymbolAddress(&ob, g_o);
  cudaGetSymbolAddress(&ga, g_a);
  cudaGetSymbolAddress(&gb, g_b);
  cudaGetSymbolAddress(&xhi, g_xhi);
  cudaGetSymbolAddress(&xlo, g_xlo);
  cudaGetSymbolAddress(&ohi, g_ohi);
  cudaGetSymbolAddress(&olo, g_olo);
  cudaGetSymbolAddress(&w3hi, g_w3hi);
  cudaGetSymbolAddress(&w3lo, g_w3lo);
  cudaGetSymbolAddress(&wohi, g_wohi);
  cudaGetSymbolAddress(&wolo, g_wolo);

  cudaFuncSetAttribute(scan_kernel, cudaFuncAttributeMaxDynamicSharedMemorySize, SCAN_SMEM);

  const int NW4 = (DIMM * DIMM) / 4;
  const int NX4 = (MM * DIMM) / 4;
  const size_t WSLAB = (size_t)DIMM * DIMM;

  split_kernel<<<(NX4 + 255) / 256, 256>>>(x, (__nv_bfloat16*)xhi, (__nv_bfloat16*)xlo, NX4);
  split_kernel<<<(NW4 + 255) / 256, 256>>>(Wq, (__nv_bfloat16*)w3hi,          (__nv_bfloat16*)w3lo,          NW4);
  split_kernel<<<(NW4 + 255) / 256, 256>>>(Wk, (__nv_bfloat16*)w3hi + WSLAB,  (__nv_bfloat16*)w3lo + WSLAB,  NW4);
  split_kernel<<<(NW4 + 255) / 256, 256>>>(Wv, (__nv_bfloat16*)w3hi + 2*WSLAB,(__nv_bfloat16*)w3lo + 2*WSLAB,NW4);
  split_kernel<<<(NW4 + 255) / 256, 256>>>(Wo, (__nv_bfloat16*)wohi, (__nv_bfloat16*)wolo, NW4);

  dim3 qkvgrid(8, MM / 128, 3);
  gemm_qkv<<<qkvgrid, 256>>>((const __nv_bfloat16*)xhi, (const __nv_bfloat16*)xlo,
                             (const __nv_bfloat16*)w3hi, (const __nv_bfloat16*)w3lo,
                             bq, bk, bv, (float*)pq, (float*)pk, (float*)pv);

  gate_gemm<<<MM / 128, 256>>>(x, Wa, ba, Wb, bb, (float*)ga, (float*)gb);

  dim3 cgrid(DIMM / 256, NN / 128, BB);
  conv_silu_kernel<<<cgrid, 256>>>((const float*)pq, conv_q, (float*)qb);
  conv_silu_kernel<<<cgrid, 256>>>((const float*)pk, conv_k, (float*)kb);
  conv_silu_kernel<<<cgrid, 256>>>((const float*)pv, conv_v, (float*)vb);

  l2norm_kernel<<<MM, 256>>>((float*)qb);
  l2norm_kernel<<<MM, 256>>>((float*)kb);

  scan_kernel<<<BB * HH, 512, SCAN_SMEM>>>((const float*)qb, (const float*)kb, (const float*)vb,
                                           (const float*)ga, (const float*)gb, (float*)ob);

  split_kernel<<<(NX4 + 255) / 256, 256>>>((const float*)ob, (__nv_bfloat16*)ohi, (__nv_bfloat16*)olo, NX4);
  dim3 ggrid(8, MM / 128);
  gemm_mma<<<ggrid, 256>>>((const __nv_bfloat16*)ohi, (const __nv_bfloat16*)olo,
                           (const __nv_bfloat16*)wohi, (const __nv_bfloat16*)wolo,
                           bo, out, 0);
}

// round 12
// speedup vs baseline: 1.0375x; 1.0286x over previous
#include <cuda_runtime.h>
#include <cuda_bf16.h>
#include <math.h>
#include <stdint.h>

#define BB   8
#define NN   2048
#define DIMM 1024
#define HH   16
#define MM   (BB*NN)   /* 16384 rows */

// ---------------- scratch (static device globals; no allocation) ----------------
__device__ float g_pq[(size_t)MM*DIMM];
__device__ float g_pk[(size_t)MM*DIMM];
__device__ float g_pv[(size_t)MM*DIMM];
__device__ float g_q [(size_t)MM*DIMM];
__device__ float g_k [(size_t)MM*DIMM];
__device__ float g_v [(size_t)MM*DIMM];
__device__ float g_a [(size_t)MM*HH];
__device__ float g_b [(size_t)MM*HH];
__device__ __align__(256) __nv_bfloat16 g_xhi[(size_t)MM*DIMM];
__device__ __align__(256) __nv_bfloat16 g_xlo[(size_t)MM*DIMM];
__device__ __align__(256) __nv_bfloat16 g_ohi[(size_t)MM*DIMM];
__device__ __align__(256) __nv_bfloat16 g_olo[(size_t)MM*DIMM];
__device__ __align__(256) __nv_bfloat16 g_w3hi[(size_t)3*DIMM*DIMM];
__device__ __align__(256) __nv_bfloat16 g_w3lo[(size_t)3*DIMM*DIMM];
__device__ __align__(256) __nv_bfloat16 g_wohi[(size_t)DIMM*DIMM];
__device__ __align__(256) __nv_bfloat16 g_wolo[(size_t)DIMM*DIMM];

// ---------------- helpers ----------------
__device__ __forceinline__ float siluf(float x){ return x / (1.f + __expf(-x)); }
__device__ __forceinline__ float sigmf(float x){ return 1.f / (1.f + __expf(-x)); }

__device__ __forceinline__ uint32_t smem_u32(const void* p){
  uint32_t a;
  asm("{ .reg .u64 t; cvta.to.shared.u64 t, %1; cvt.u32.u64 %0, t; }" : "=r"(a) : "l"(p));
  return a;
}
__device__ __forceinline__ void ldsm4(uint32_t* d, uint32_t addr){
  asm volatile("ldmatrix.sync.aligned.m8n8.x4.shared.b16 {%0,%1,%2,%3}, [%4];"
    : "=r"(d[0]),"=r"(d[1]),"=r"(d[2]),"=r"(d[3]) : "r"(addr));
}
__device__ __forceinline__ void mma16816(float* d, const uint32_t* a, const uint32_t* b){
  asm volatile("mma.sync.aligned.m16n8k16.row.col.f32.bf16.bf16.f32 "
    "{%0,%1,%2,%3}, {%4,%5,%6,%7}, {%8,%9}, {%0,%1,%2,%3};"
    : "+f"(d[0]),"+f"(d[1]),"+f"(d[2]),"+f"(d[3])
    : "r"(a[0]),"r"(a[1]),"r"(a[2]),"r"(a[3]), "r"(b[0]),"r"(b[1]));
}

// ---------------- bf16 hi/lo split ----------------
__global__ __launch_bounds__(256) void split_kernel(
    const float* __restrict__ X, __nv_bfloat16* __restrict__ Hp, __nv_bfloat16* __restrict__ Lp, int n4)
{
  int i = blockIdx.x * 256 + threadIdx.x;
  if (i >= n4) return;
  float4 v = ((const float4*)X)[i];
  __nv_bfloat16 h0 = __float2bfloat16(v.x), h1 = __float2bfloat16(v.y);
  __nv_bfloat16 h2 = __float2bfloat16(v.z), h3 = __float2bfloat16(v.w);
  __nv_bfloat16 l0 = __float2bfloat16(v.x - __bfloat162float(h0));
  __nv_bfloat16 l1 = __float2bfloat16(v.y - __bfloat162float(h1));
  __nv_bfloat16 l2 = __float2bfloat16(v.z - __bfloat162float(h2));
  __nv_bfloat16 l3 = __float2bfloat16(v.w - __bfloat162float(h3));
  __nv_bfloat162* Hq = (__nv_bfloat162*)Hp;
  __nv_bfloat162* Lq = (__nv_bfloat162*)Lp;
  Hq[2*i]   = __nv_bfloat162(h0, h1);
  Hq[2*i+1] = __nv_bfloat162(h2, h3);
  Lq[2*i]   = __nv_bfloat162(l0, l1);
  Lq[2*i+1] = __nv_bfloat162(l2, l3);
}

// ---------------- HMMA bf16-split GEMM (proven R8 design) ----------------
#define KC 32
#define ASTR 40          /* bf16 row stride (80 B, 16B-mult, conflict-free) */

__global__ __launch_bounds__(256, 1) void gemm_mma(
    const __nv_bfloat16* __restrict__ Ahi, const __nv_bfloat16* __restrict__ Alo,
    const __nv_bfloat16* __restrict__ Whi, const __nv_bfloat16* __restrict__ Wlo,
    const float* __restrict__ bias, float* __restrict__ C, int doSilu)
{
  __shared__ __nv_bfloat16 sAh[128*ASTR], sAl[128*ASTR], sWh[128*ASTR], sWl[128*ASTR];

  const int tid  = threadIdx.x;
  const int w    = tid >> 5;
  const int lane = tid & 31;
  const int warp_m = w >> 2;
  const int warp_n = w & 3;
  const int m0 = blockIdx.y << 7;
  const int n0 = blockIdx.x << 7;

  const int r    = tid >> 1;
  const int gcol = (tid & 1) << 4;
  const __nv_bfloat16* pAh = Ahi + (size_t)(m0 + r) * DIMM + gcol;
  const __nv_bfloat16* pAl = Alo + (size_t)(m0 + r) * DIMM + gcol;
  const __nv_bfloat16* pWh = Whi + (size_t)(n0 + r) * DIMM + gcol;
  const __nv_bfloat16* pWl = Wlo + (size_t)(n0 + r) * DIMM + gcol;
  const int soff = r * ASTR + gcol;

  const int mmat = lane >> 3, rr = lane & 7;
  const int arowb = warp_m * 64 + ((mmat & 1) << 3) + rr;
  const int acols = (mmat >> 1) << 3;
  const int browb = warp_n * 32 + ((mmat >> 1) << 3) + rr;
  const int bcols = (mmat & 1) << 3;
  const uint32_t sAhB = smem_u32(sAh), sAlB = smem_u32(sAl);
  const uint32_t sWhB = smem_u32(sWh), sWlB = smem_u32(sWl);

  float acc[4][4][4];
#pragma unroll
  for (int mt = 0; mt < 4; mt++)
#pragma unroll
    for (int nt = 0; nt < 4; nt++)
#pragma unroll
      for (int i = 0; i < 4; i++) acc[mt][nt][i] = 0.f;

  uint4 rAh[2], rAl[2], rWh[2], rWl[2];
  rAh[0] = *(const uint4*)(pAh);     rAh[1] = *(const uint4*)(pAh + 8);
  rAl[0] = *(const uint4*)(pAl);     rAl[1] = *(const uint4*)(pAl + 8);
  rWh[0] = *(const uint4*)(pWh);     rWh[1] = *(const uint4*)(pWh + 8);
  rWl[0] = *(const uint4*)(pWl);     rWl[1] = *(const uint4*)(pWl + 8);

  for (int c = 0; c < DIMM / KC; c++) {
    __syncthreads();
    *(uint4*)&sAh[soff]     = rAh[0];  *(uint4*)&sAh[soff + 8] = rAh[1];
    *(uint4*)&sAl[soff]     = rAl[0];  *(uint4*)&sAl[soff + 8] = rAl[1];
    *(uint4*)&sWh[soff]     = rWh[0];  *(uint4*)&sWh[soff + 8] = rWh[1];
    *(uint4*)&sWl[soff]     = rWl[0];  *(uint4*)&sWl[soff + 8] = rWl[1];
    if (c + 1 < DIMM / KC) {
      const int ko = (c + 1) * KC;
      rAh[0] = *(const uint4*)(pAh + ko);  rAh[1] = *(const uint4*)(pAh + ko + 8);
      rAl[0] = *(const uint4*)(pAl + ko);  rAl[1] = *(const uint4*)(pAl + ko + 8);
      rWh[0] = *(const uint4*)(pWh + ko);  rWh[1] = *(const uint4*)(pWh + ko + 8);
      rWl[0] = *(const uint4*)(pWl + ko);  rWl[1] = *(const uint4*)(pWl + ko + 8);
    }
    __syncthreads();

#pragma unroll
    for (int ks = 0; ks < KC; ks += 16) {
      uint32_t ah[4][4], al[4][4];
#pragma unroll
      for (int mt = 0; mt < 4; mt++) {
        uint32_t off = (uint32_t)(((arowb + mt * 16) * ASTR + ks + acols) * 2);
        ldsm4(ah[mt], sAhB + off);
        ldsm4(al[mt], sAlB + off);
      }
      uint32_t bh[4][2], bl[4][2];
#pragma unroll
      for (int np = 0; np < 2; np++) {
        uint32_t off = (uint32_t)(((browb + np * 16) * ASTR + ks + bcols) * 2);
        uint32_t t[4];
        ldsm4(t, sWhB + off);
        bh[2*np][0] = t[0]; bh[2*np][1] = t[1]; bh[2*np+1][0] = t[2]; bh[2*np+1][1] = t[3];
        ldsm4(t, sWlB + off);
        bl[2*np][0] = t[0]; bl[2*np][1] = t[1]; bl[2*np+1][0] = t[2]; bl[2*np+1][1] = t[3];
      }
#pragma unroll
      for (int mt = 0; mt < 4; mt++)
#pragma unroll
        for (int nt = 0; nt < 4; nt++) {
          mma16816(acc[mt][nt], ah[mt], bh[nt]);
          mma16816(acc[mt][nt], ah[mt], bl[nt]);
          mma16816(acc[mt][nt], al[mt], bh[nt]);
        }
    }
  }

  const int lr = lane >> 2;
  const int lc = (lane & 3) << 1;
#pragma unroll
  for (int mt = 0; mt < 4; mt++) {
    const int row0 = m0 + warp_m * 64 + mt * 16 + lr;
#pragma unroll
    for (int nt = 0; nt < 4; nt++) {
      const int col = n0 + warp_n * 32 + nt * 8 + lc;
      const float b0 = bias[col], b1 = bias[col + 1];
      float v0 = acc[mt][nt][0] + b0;
      float v1 = acc[mt][nt][1] + b1;
      float v2 = acc[mt][nt][2] + b0;
      float v3 = acc[mt][nt][3] + b1;
      if (doSilu) { v0 = siluf(v0); v1 = siluf(v1); v2 = siluf(v2); v3 = siluf(v3); }
      *(float2*)(C + (size_t)row0 * DIMM + col)       = make_float2(v0, v1);
      *(float2*)(C + (size_t)(row0 + 8) * DIMM + col) = make_float2(v2, v3);
    }
  }
}

// ---------------- gate projections ----------------
__global__ __launch_bounds__(256) void gate_gemm(
    const float* __restrict__ X, const float* __restrict__ Wa, const float* __restrict__ ba,
    const float* __restrict__ Wb, const float* __restrict__ bbias,
    float* __restrict__ Ga, float* __restrict__ Gb)
{
  __shared__ float Xs[32][129];
  __shared__ float Ws[32][33];
  const int tid = threadIdx.x;
  const int m0  = blockIdx.x << 7;
  const int tm0 = (tid >> 4) << 3;
  const int tn0 = (tid & 15) << 1;

  float acc[8][2];
#pragma unroll
  for (int i = 0; i < 8; i++) { acc[i][0] = 0.f; acc[i][1] = 0.f; }

  for (int k0 = 0; k0 < 1024; k0 += 32) {
    __syncthreads();
#pragma unroll
    for (int ii = 0; ii < 4; ii++) {
      int idx = tid + (ii << 8);
      int rr = idx >> 3, c4 = (idx & 7) << 2;
      float4 v = *(const float4*)&X[(size_t)(m0 + rr) * DIMM + k0 + c4];
      Xs[c4+0][rr] = v.x; Xs[c4+1][rr] = v.y; Xs[c4+2][rr] = v.z; Xs[c4+3][rr] = v.w;
    }
    {
      int n = tid >> 3, c4 = (tid & 7) << 2;
      if (n < 32) {
        const float* wp = (n < 16) ? (Wa + (size_t)n * DIMM) : (Wb + (size_t)(n - 16) * DIMM);
        float4 v = *(const float4*)&wp[k0 + c4];
        Ws[c4+0][n] = v.x; Ws[c4+1][n] = v.y; Ws[c4+2][n] = v.z; Ws[c4+3][n] = v.w;
      }
    }
    __syncthreads();
#pragma unroll
    for (int kk = 0; kk < 32; kk++) {
      float wf0 = Ws[kk][tn0], wf1 = Ws[kk][tn0 + 1];
#pragma unroll
      for (int i = 0; i < 8; i++) {
        float av = Xs[kk][tm0 + i];
        acc[i][0] = fmaf(av, wf0, acc[i][0]);
        acc[i][1] = fmaf(av, wf1, acc[i][1]);
      }
    }
  }
#pragma unroll
  for (int j = 0; j < 2; j++) {
    int col = tn0 + j;
    float bi = (col < 16) ? ba[col] : bbias[col - 16];
    float* dst = (col < 16) ? Ga : Gb;
    int cc = col & 15;
#pragma unroll
    for (int i = 0; i < 8; i++) {
      int row = m0 + tm0 + i;
      dst[(size_t)row * 16 + cc] = sigmf(acc[i][j] + bi);
    }
  }
}

// ---------------- depthwise conv (K=4) + silu (for v) ----------------
__global__ __launch_bounds__(256) void conv_silu_kernel(
    const float* __restrict__ P, const float* __restrict__ wc, float* __restrict__ Y)
{
  const int c  = (blockIdx.x << 8) + threadIdx.x;
  const int b  = blockIdx.z;
  const int t0 = blockIdx.y << 7;
  const float w0 = wc[c*4+0], w1 = wc[c*4+1], w2 = wc[c*4+2], w3 = wc[c*4+3];
  const float* base  = P + (size_t)b * NN * DIMM + c;
  float*       ybase = Y + (size_t)b * NN * DIMM + c;
  float xm2 = (t0 >= 2) ? base[(size_t)(t0-2)*DIMM] : 0.f;
  float xm1 = (t0 >= 1) ? base[(size_t)(t0-1)*DIMM] : 0.f;
  float x0  = base[(size_t)t0 * DIMM];
#pragma unroll 4
  for (int t = t0; t < t0 + 128; t++) {
    float xp1 = (t + 1 < NN) ? base[(size_t)(t+1)*DIMM] : 0.f;
    float y = w0*xm2 + w1*xm1 + w2*x0 + w3*xp1;
    ybase[(size_t)t * DIMM] = siluf(y);
    xm2 = xm1; xm1 = x0; x0 = xp1;
  }
}

// ---------------- fused conv(K=4)+silu+l2norm (for q,k) ----------------
// Block = (b, 8 timesteps), all 1024 channels. Window 11 rows in smem.
#define CT 8
__global__ __launch_bounds__(256) void conv_norm_kernel(
    const float* __restrict__ P, const float* __restrict__ wc, float* __restrict__ Y)
{
  __shared__ float win[11*1024];
  __shared__ float wsum[CT][9];
  __shared__ float inv[CT];
  const int tid = threadIdx.x;
  const int b  = blockIdx.y;
  const int t0 = blockIdx.x * CT;
  const float* base = P + (size_t)b * NN * DIMM;

  // load 11 rows (t0-2 .. t0+8), zero-padded
  for (int i = tid; i < 11*256; i += 256) {
    int row = i >> 8, c4 = (i & 255) << 2;
    int t = t0 - 2 + row;
    float4 v = (t >= 0 && t < NN) ? *(const float4*)(base + (size_t)t*DIMM + c4)
                                  : make_float4(0.f,0.f,0.f,0.f);
    *(float4*)&win[row*1024 + c4] = v;
  }
  __syncthreads();

  const int c0 = tid << 2;          // 4 channels per thread
  float wgt[4][4];
#pragma unroll
  for (int j = 0; j < 4; j++) {
    float4 w4 = *(const float4*)&wc[(c0 + j) * 4];
    wgt[j][0] = w4.x; wgt[j][1] = w4.y; wgt[j][2] = w4.z; wgt[j][3] = w4.w;
  }

  float yv[CT][4];
  float part[CT];
#pragma unroll
  for (int lt = 0; lt < CT; lt++) {
    float ss = 0.f;
#pragma unroll
    for (int j = 0; j < 4; j++) {
      float y = wgt[j][0]*win[(lt+0)*1024 + c0 + j]
              + wgt[j][1]*win[(lt+1)*1024 + c0 + j]
              + wgt[j][2]*win[(lt+2)*1024 + c0 + j]
              + wgt[j][3]*win[(lt+3)*1024 + c0 + j];
      y = siluf(y);
      yv[lt][j] = y;
      ss = fmaf(y, y, ss);
    }
    part[lt] = ss;
  }
  // warp reduce each part
#pragma unroll
  for (int lt = 0; lt < CT; lt++) {
    float s = part[lt];
#pragma unroll
    for (int o = 16; o > 0; o >>= 1) s += __shfl_xor_sync(0xffffffffu, s, o);
    if ((tid & 31) == 0) wsum[lt][tid >> 5] = s;
  }
  __syncthreads();
  if (tid < CT) {
    float s = wsum[tid][0]+wsum[tid][1]+wsum[tid][2]+wsum[tid][3]
            + wsum[tid][4]+wsum[tid][5]+wsum[tid][6]+wsum[tid][7];
    inv[tid] = 1.f / (sqrtf(s) + 1e-6f);
  }
  __syncthreads();
#pragma unroll
  for (int lt = 0; lt < CT; lt++) {
    float iv = inv[lt];
    float4 o4 = make_float4(yv[lt][0]*iv, yv[lt][1]*iv, yv[lt][2]*iv, yv[lt][3]*iv);
    *(float4*)(Y + (size_t)b*NN*DIMM + (size_t)(t0+lt)*DIMM + c0) = o4;
  }
}

// ---------------- chunked gated delta-rule scan (WY form, bf16 output) --------
#define SPAD 68
#define SCAN_FLOATS (4352*2 + 2176*5 + 1056*3 + 96)
#define SCAN_SMEM   (SCAN_FLOATS*4)

__global__ __launch_bounds__(512, 1) void scan_kernel(
    const float* __restrict__ Qg, const float* __restrict__ Kg, const float* __restrict__ Vg,
    const float* __restrict__ Ag, const float* __restrict__ Bgg,
    __nv_bfloat16* __restrict__ Ohi, __nv_bfloat16* __restrict__ Olo)
{
  extern __shared__ float sm[];
  float* S   = sm;                 // [64][68]
  float* T   = sm + 4352;         // S^T [64][68]
  float* q   = sm + 8704;         // [32][68]
  float* kkk = sm + 10880;        // [32][68]
  float* vvv = sm + 13056;        // [32][68]
  float* W   = sm + 15232;        // [32][68]
  float* YZ  = sm + 17408;        // [32][68]
  float* D   = sm + 19584;        // [32][33]
  float* Gb  = sm + 20640;        // [32][33]
  float* Hm  = sm + 21696;        // [32][33]
  float* aa  = sm + 22752;
  float* bb  = sm + 22784;
  float* Ac  = sm + 22816;

  const int tid = threadIdx.x;
  const int bh = blockIdx.x;
  const int b = bh >> 4, h = bh & 15;
  const size_t base = ((size_t)b * NN) * DIMM + h * 64;

  for (int i = tid; i < 4352*2; i += 512) sm[i] = 0.f;
  __syncthreads();

  for (int t0 = 0; t0 < NN; t0 += 32) {
#pragma unroll
    for (int j = 0; j < 4; j++) {
      int idx = tid + (j << 9);
      int t = idx >> 6, e = idx & 63;
      size_t off = base + (size_t)(t0 + t) * DIMM + e;
      q[t*SPAD+e] = Qg[off]; kkk[t*SPAD+e] = Kg[off]; vvv[t*SPAD+e] = Vg[off];
    }
    if (tid < 32) {
      size_t off = ((size_t)b * NN + t0 + tid) * 16 + h;
      aa[tid] = Ag[off]; bb[tid] = Bgg[off];
    }
    __syncthreads();

    if (tid < 32) {
      int s = tid;
      float d = 1.f;
      D[s*33 + s] = 1.f;
      for (int t = s + 1; t < 32; t++) { d *= aa[t]; D[t*33 + s] = d; }
      float p = 1.f;
      for (int r = 0; r <= s; r++) p *= aa[r];
      Ac[s] = p;
    }
    {
      int d = tid & 63, tb = tid >> 6;
      float acc0=0.f, acc1=0.f, acc2=0.f, acc3=0.f;
      for (int e = 0; e < 64; e++) {
        float tv = T[e*SPAD + d];
        acc0 = fmaf(kkk[(tb+ 0)*SPAD+e], tv, acc0);
        acc1 = fmaf(kkk[(tb+ 8)*SPAD+e], tv, acc1);
        acc2 = fmaf(kkk[(tb+16)*SPAD+e], tv, acc2);
        acc3 = fmaf(kkk[(tb+24)*SPAD+e], tv, acc3);
      }
      YZ[(tb+ 0)*SPAD+d] = acc0; YZ[(tb+ 8)*SPAD+d] = acc1;
      YZ[(tb+16)*SPAD+d] = acc2; YZ[(tb+24)*SPAD+d] = acc3;
    }
    __syncthreads();

#pragma unroll
    for (int j = 0; j < 2; j++) {
      int idx = tid + (j << 9);
      int s = idx >> 5, t = idx & 31;
      if (s < t) {
        const float4* ks = (const float4*)(kkk + s*SPAD);
        const float4* kt = (const float4*)(kkk + t*SPAD);
        float dot = 0.f;
#pragma unroll
        for (int e4 = 0; e4 < 16; e4++) {
          float4 x = ks[e4], y = kt[e4];
          dot += x.x*y.x + x.y*y.y + x.z*y.z + x.w*y.w;
        }
        Gb[s*33 + t] = bb[t] * D[t*33 + s] * dot;
      }
    }
    __syncthreads();

    if (tid < 64) {
      int d = tid;
      float w[32];
#pragma unroll
      for (int t = 0; t < 32; t++) {
        float acc = 0.f;
#pragma unroll
        for (int s = 0; s < t; s++) acc = fmaf(Gb[s*33 + t], w[s], acc);
        w[t] = bb[t] * (vvv[t*SPAD + d] - Ac[t] * YZ[t*SPAD + d]) - acc;
        W[t*SPAD + d] = w[t];
      }
    }
    __syncthreads();

#pragma unroll
    for (int j = 0; j < 2; j++) {
      int idx = tid + (j << 9);
      int t = idx >> 5, s = idx & 31;
      if (s <= t) {
        const float4* qt = (const float4*)(q + t*SPAD);
        const float4* ws = (const float4*)(W + s*SPAD);
        float dot = 0.f;
#pragma unroll
        for (int d4 = 0; d4 < 16; d4++) {
          float4 x = qt[d4], y = ws[d4];
          dot += x.x*y.x + x.y*y.y + x.z*y.z + x.w*y.w;
        }
        Hm[t*33 + s] = D[t*33 + s] * dot;
      }
    }
    {
      int e = tid & 63, tb = tid >> 6;
      float acc0=0.f, acc1=0.f, acc2=0.f, acc3=0.f;
      for (int d = 0; d < 64; d++) {
        float sv = S[d*SPAD + e];
        acc0 = fmaf(q[(tb+ 0)*SPAD+d], sv, acc0);
        acc1 = fmaf(q[(tb+ 8)*SPAD+d], sv, acc1);
        acc2 = fmaf(q[(tb+16)*SPAD+d], sv, acc2);
        acc3 = fmaf(q[(tb+24)*SPAD+d], sv, acc3);
      }
      __syncthreads();
      YZ[(tb+ 0)*SPAD+e] = acc0; YZ[(tb+ 8)*SPAD+e] = acc1;
      YZ[(tb+16)*SPAD+e] = acc2; YZ[(tb+24)*SPAD+e] = acc3;
    }
    __syncthreads();

    {
      int e = tid & 63, tb = tid >> 6;
#pragma unroll
      for (int j = 0; j < 4; j++) {
        int t = tb + (j << 3);
        float acc = Ac[t] * YZ[t*SPAD + e];
        for (int s = 0; s <= t; s++) acc = fmaf(Hm[t*33 + s], kkk[s*SPAD + e], acc);
        __nv_bfloat16 hh = __float2bfloat16(acc);
        __nv_bfloat16 ll = __float2bfloat16(acc - __bfloat162float(hh));
        size_t off = base + (size_t)(t0 + t) * DIMM + e;
        Ohi[off] = hh;
        Olo[off] = ll;
      }
    }
    {
      int e = tid & 63, db = tid >> 6;
      float acc[8];
#pragma unroll
      for (int j = 0; j < 8; j++) acc[j] = Ac[31] * S[(db + (j<<3))*SPAD + e];
      for (int s = 0; s < 32; s++) {
        float t1 = D[31*33 + s] * kkk[s*SPAD + e];
#pragma unroll
        for (int j = 0; j < 8; j++) acc[j] = fmaf(W[s*SPAD + db + (j<<3)], t1, acc[j]);
      }
#pragma unroll
      for (int j = 0; j < 8; j++) S[(db + (j<<3))*SPAD + e] = acc[j];
    }
    {
      int d = tid & 63, eb = tid >> 6;
      float acc[8];
#pragma unroll
      for (int j = 0; j < 8; j++) acc[j] = Ac[31] * T[(eb + (j<<3))*SPAD + d];
      for (int s = 0; s < 32; s++) {
        float t1 = D[31*33 + s] * W[s*SPAD + d];
#pragma unroll
        for (int j = 0; j < 8; j++) acc[j] = fmaf(kkk[s*SPAD + eb + (j<<3)], t1, acc[j]);
      }
#pragma unroll
      for (int j = 0; j < 8; j++) T[(eb + (j<<3))*SPAD + d] = acc[j];
    }
    __syncthreads();
  }
}

// ---------------- launch ----------------
extern "C" void kernel_launch(void* const* d_in, const int* in_sizes, int n_in,
                              void* d_out, int out_size) {
  const float* x      = (const float*)d_in[0];
  const float* Wq     = (const float*)d_in[1];
  const float* bq     = (const float*)d_in[2];
  const float* Wk     = (const float*)d_in[3];
  const float* bk     = (const float*)d_in[4];
  const float* Wv     = (const float*)d_in[5];
  const float* bv     = (const float*)d_in[6];
  const float* Wa     = (const float*)d_in[7];
  const float* ba     = (const float*)d_in[8];
  const float* Wb     = (const float*)d_in[9];
  const float* bb     = (const float*)d_in[10];
  const float* conv_q = (const float*)d_in[11];
  const float* conv_k = (const float*)d_in[12];
  const float* conv_v = (const float*)d_in[13];
  const float* Wo     = (const float*)d_in[14];
  const float* bo     = (const float*)d_in[15];
  float* out = (float*)d_out;

  void *pq, *pk, *pv, *qb, *kb, *vb, *ga, *gb;
  void *xhi, *xlo, *ohi, *olo, *w3hi, *w3lo, *wohi, *wolo;
  cudaGetSymbolAddress(&pq, g_pq);
  cudaGetSymbolAddress(&pk, g_pk);
  cudaGetSymbolAddress(&pv, g_pv);
  cudaGetSymbolAddress(&qb, g_q);
  cudaGetSymbolAddress(&vb, g_v);
  cudaGetSymbolAddress(&kb, g_k);
  cudaGetSymbolAddress(&ga, g_a);
  cudaGetSymbolAddress(&gb, g_b);
  cudaGetSymbolAddress(&xhi, g_xhi);
  cudaGetSymbolAddress(&xlo, g_xlo);
  cudaGetSymbolAddress(&ohi, g_ohi);
  cudaGetSymbolAddress(&olo, g_olo);
  cudaGetSymbolAddress(&w3hi, g_w3hi);
  cudaGetSymbolAddress(&w3lo, g_w3lo);
  cudaGetSymbolAddress(&wohi, g_wohi);
  cudaGetSymbolAddress(&wolo, g_wolo);

  cudaFuncSetAttribute(scan_kernel, cudaFuncAttributeMaxDynamicSharedMemorySize, SCAN_SMEM);

  const int NW4 = (DIMM * DIMM) / 4;
  const int NX4 = (MM * DIMM) / 4;
  const size_t WSLAB = (size_t)DIMM * DIMM;

  split_kernel<<<(NX4 + 255) / 256, 256>>>(x, (__nv_bfloat16*)xhi, (__nv_bfloat16*)xlo, NX4);
  split_kernel<<<(NW4 + 255) / 256, 256>>>(Wq, (__nv_bfloat16*)w3hi,          (__nv_bfloat16*)w3lo,          NW4);
  split_kernel<<<(NW4 + 255) / 256, 256>>>(Wk, (__nv_bfloat16*)w3hi + WSLAB,  (__nv_bfloat16*)w3lo + WSLAB,  NW4);
  split_kernel<<<(NW4 + 255) / 256, 256>>>(Wv, (__nv_bfloat16*)w3hi + 2*WSLAB,(__nv_bfloat16*)w3lo + 2*WSLAB,NW4);
  split_kernel<<<(NW4 + 255) / 256, 256>>>(Wo, (__nv_bfloat16*)wohi, (__nv_bfloat16*)wolo, NW4);

  dim3 ggrid(8, MM / 128);
  gemm_mma<<<ggrid, 256>>>((const __nv_bfloat16*)xhi, (const __nv_bfloat16*)xlo,
                           (const __nv_bfloat16*)w3hi, (const __nv_bfloat16*)w3lo,
                           bq, (float*)pq, 1);
  gemm_mma<<<ggrid, 256>>>((const __nv_bfloat16*)xhi, (const __nv_bfloat16*)xlo,
                           (const __nv_bfloat16*)w3hi + WSLAB, (const __nv_bfloat16*)w3lo + WSLAB,
                           bk, (float*)pk, 1);
  gemm_mma<<<ggrid, 256>>>((const __nv_bfloat16*)xhi, (const __nv_bfloat16*)xlo,
                           (const __nv_bfloat16*)w3hi + 2*WSLAB, (const __nv_bfloat16*)w3lo + 2*WSLAB,
                           bv, (float*)pv, 1);

  gate_gemm<<<MM / 128, 256>>>(x, Wa, ba, Wb, bb, (float*)ga, (float*)gb);

  dim3 ngrid(NN / CT, BB);
  conv_norm_kernel<<<ngrid, 256>>>((const float*)pq, conv_q, (float*)qb);
  conv_norm_kernel<<<ngrid, 256>>>((const float*)pk, conv_k, (float*)kb);
  dim3 cgrid(DIMM / 256, NN / 128, BB);
  conv_silu_kernel<<<cgrid, 256>>>((const float*)pv, conv_v, (float*)vb);

  scan_kernel<<<BB * HH, 512, SCAN_SMEM>>>((const float*)qb, (const float*)kb, (const float*)vb,
                                           (const float*)ga, (const float*)gb,
                                           (__nv_bfloat16*)ohi, (__nv_bfloat16*)olo);

  gemm_mma<<<ggrid, 256>>>((const __nv_bfloat16*)ohi, (const __nv_bfloat16*)olo,
                           (const __nv_bfloat16*)wohi, (const __nv_bfloat16*)wolo,
                           bo, out, 0);
}